// round 1
// baseline (speedup 1.0000x reference)
#include <cuda_runtime.h>
#include <math.h>

// Problem shapes (fixed by reference)
#define T_STEPS 512
#define BATCH   256
#define NIN     1024
#define NH      1024

// ============================================================================
// Phase 1 GEMM: C[M,N] = A[M,K] @ W[K,N] + bias[N]
// M = T*B = 131072, K = NIN = 1024, N = NH = 1024
// 128x128 tile, BK=8, 256 threads, 8x8 per thread, float4 everywhere.
// ============================================================================
__global__ __launch_bounds__(256) void gemm_xw_kernel(
    const float* __restrict__ A, const float* __restrict__ W,
    const float* __restrict__ bias, float* __restrict__ C)
{
    const int K = NIN, N = NH;
    __shared__ float As[8][128 + 4];   // transposed A tile, padded
    __shared__ float Ws[8][128];

    const int tid = threadIdx.x;
    const int m0 = blockIdx.y * 128;
    const int n0 = blockIdx.x * 128;

    // A tile load map: 128 rows x 8 cols = 256 float4 -> 1/thread
    const int aRow = tid >> 1;            // 0..127
    const int aCol = (tid & 1) * 4;       // 0 or 4
    // W tile load map: 8 rows x 128 cols = 256 float4 -> 1/thread
    const int wRow = tid >> 5;            // 0..7
    const int wCol = (tid & 31) * 4;      // 0..124

    // Compute map: 16x16 thread grid, 8x8 per thread
    const int tRow = (tid >> 4) * 8;      // 0..120
    const int tCol = (tid & 15) * 8;      // 0..120

    float acc[8][8];
#pragma unroll
    for (int i = 0; i < 8; i++)
#pragma unroll
        for (int j = 0; j < 8; j++) acc[i][j] = 0.f;

    const float* Ap = A + (size_t)(m0 + aRow) * K + aCol;
    const float* Wp = W + (size_t)wRow * N + n0 + wCol;

    for (int k0 = 0; k0 < K; k0 += 8) {
        float4 a4 = *(const float4*)(Ap + k0);
        As[aCol + 0][aRow] = a4.x;
        As[aCol + 1][aRow] = a4.y;
        As[aCol + 2][aRow] = a4.z;
        As[aCol + 3][aRow] = a4.w;
        *(float4*)(&Ws[wRow][wCol]) = *(const float4*)(Wp + (size_t)k0 * N);
        __syncthreads();
#pragma unroll
        for (int k = 0; k < 8; k++) {
            float ar[8], wr[8];
            *(float4*)(ar)     = *(const float4*)(&As[k][tRow]);
            *(float4*)(ar + 4) = *(const float4*)(&As[k][tRow + 4]);
            *(float4*)(wr)     = *(const float4*)(&Ws[k][tCol]);
            *(float4*)(wr + 4) = *(const float4*)(&Ws[k][tCol + 4]);
#pragma unroll
            for (int i = 0; i < 8; i++)
#pragma unroll
                for (int j = 0; j < 8; j++)
                    acc[i][j] += ar[i] * wr[j];
        }
        __syncthreads();
    }

    float bv[8];
    *(float4*)(bv)     = *(const float4*)(bias + n0 + tCol);
    *(float4*)(bv + 4) = *(const float4*)(bias + n0 + tCol + 4);
#pragma unroll
    for (int i = 0; i < 8; i++) {
        float4 o0, o1;
        o0.x = acc[i][0] + bv[0]; o0.y = acc[i][1] + bv[1];
        o0.z = acc[i][2] + bv[2]; o0.w = acc[i][3] + bv[3];
        o1.x = acc[i][4] + bv[4]; o1.y = acc[i][5] + bv[5];
        o1.z = acc[i][6] + bv[6]; o1.w = acc[i][7] + bv[7];
        float* cp = C + (size_t)(m0 + tRow + i) * N + n0 + tCol;
        *(float4*)(cp)     = o0;
        *(float4*)(cp + 4) = o1;
    }
}

// ============================================================================
// t = 0: out[0] = tanh(xw[0])   (state0 is zero, so no W_hh GEMM)
// ============================================================================
__global__ void tanh0_kernel(float* __restrict__ x)
{
    int idx = blockIdx.x * blockDim.x + threadIdx.x;
    float4* p = (float4*)x + idx;
    float4 v = *p;
    v.x = tanhf(v.x); v.y = tanhf(v.y); v.z = tanhf(v.z); v.w = tanhf(v.w);
    *p = v;
}

// ============================================================================
// RNN step: XW[m,n] = tanh(XW[m,n] + sum_k Hprev[m,k] * W[k,n])
// M = 256, K = N = 1024. Tile 32x64, BK=16, 128 threads, 4x4 per thread.
// Register prefetch of the next K-tile to hide L2 latency (1 warp/SMSP).
// Grid: (N/64=16, M/32=8) = 128 blocks -> ~1 block per SM.
// ============================================================================
__global__ __launch_bounds__(128) void rnn_step_kernel(
    const float* __restrict__ Hprev,   // [BATCH, NH]  (= out[t-1], already tanh'd)
    const float* __restrict__ W,       // [NH, NH]
    float* __restrict__ XW)            // [BATCH, NH]  in/out (= out[t])
{
    const int K = NH, N = NH;
    __shared__ float Hs[16][32 + 4];   // transposed H tile, padded
    __shared__ float Ws[16][64];

    const int tid = threadIdx.x;
    const int m0 = blockIdx.y * 32;
    const int n0 = blockIdx.x * 64;

    // H tile load: 32 rows x 16 cols = 128 float4 -> 1/thread
    const int hRow = tid >> 2;            // 0..31
    const int hCol = (tid & 3) * 4;       // 0..12
    // W tile load: 16 rows x 64 cols = 256 float4 -> 2/thread
    const int wRow = tid >> 4;            // 0..7  (second: +8)
    const int wCol = (tid & 15) * 4;      // 0..60

    // Compute map: 8x16 thread grid, 4x4 per thread
    const int tRow = (tid >> 4) * 4;      // 0..28
    const int tCol = (tid & 15) * 4;      // 0..60

    float acc[4][4];
#pragma unroll
    for (int i = 0; i < 4; i++)
#pragma unroll
        for (int j = 0; j < 4; j++) acc[i][j] = 0.f;

    const float* Hp = Hprev + (size_t)(m0 + hRow) * K + hCol;
    const float* Wp = W + n0 + wCol;

    // Prefetch first tile into registers
    float4 hreg  = *(const float4*)(Hp);
    float4 wreg0 = *(const float4*)(Wp + (size_t)(wRow)     * N);
    float4 wreg1 = *(const float4*)(Wp + (size_t)(wRow + 8) * N);

    for (int k0 = 0; k0 < K; k0 += 16) {
        Hs[hCol + 0][hRow] = hreg.x;
        Hs[hCol + 1][hRow] = hreg.y;
        Hs[hCol + 2][hRow] = hreg.z;
        Hs[hCol + 3][hRow] = hreg.w;
        *(float4*)(&Ws[wRow][wCol])     = wreg0;
        *(float4*)(&Ws[wRow + 8][wCol]) = wreg1;
        __syncthreads();

        // Prefetch next tile while computing this one
        if (k0 + 16 < K) {
            hreg  = *(const float4*)(Hp + k0 + 16);
            wreg0 = *(const float4*)(Wp + (size_t)(k0 + 16 + wRow)     * N);
            wreg1 = *(const float4*)(Wp + (size_t)(k0 + 16 + wRow + 8) * N);
        }

#pragma unroll
        for (int k = 0; k < 16; k++) {
            float hr[4], wr[4];
            *(float4*)hr = *(const float4*)(&Hs[k][tRow]);
            *(float4*)wr = *(const float4*)(&Ws[k][tCol]);
#pragma unroll
            for (int i = 0; i < 4; i++)
#pragma unroll
                for (int j = 0; j < 4; j++)
                    acc[i][j] += hr[i] * wr[j];
        }
        __syncthreads();
    }

    // Epilogue: add precomputed xw (in place), tanh, write back
#pragma unroll
    for (int i = 0; i < 4; i++) {
        float* xp = XW + (size_t)(m0 + tRow + i) * N + n0 + tCol;
        float4 x4 = *(const float4*)xp;
        x4.x = tanhf(x4.x + acc[i][0]);
        x4.y = tanhf(x4.y + acc[i][1]);
        x4.z = tanhf(x4.z + acc[i][2]);
        x4.w = tanhf(x4.w + acc[i][3]);
        *(float4*)xp = x4;
    }
}

// ============================================================================
// Copy final state (= out[T-1]) to the tail of the output buffer.
// ============================================================================
__global__ void copy_final_kernel(const float* __restrict__ src,
                                  float* __restrict__ dst)
{
    int idx = blockIdx.x * blockDim.x + threadIdx.x;
    ((float4*)dst)[idx] = ((const float4*)src)[idx];
}

// ============================================================================
// Launch
// ============================================================================
extern "C" void kernel_launch(void* const* d_in, const int* in_sizes, int n_in,
                              void* d_out, int out_size)
{
    const float* inputs = (const float*)d_in[0];   // [T, B, NIN]
    const float* W_xh   = (const float*)d_in[1];   // [NIN, NH]
    const float* W_hh   = (const float*)d_in[2];   // [NH, NH]
    const float* b_h    = (const float*)d_in[3];   // [NH]
    float* out = (float*)d_out;                    // [T, B, NH] + [B, NH]

    const size_t step_elems = (size_t)BATCH * NH;  // 262144

    // Phase 1: xw = inputs @ W_xh + b_h, written in place into out[0..T)
    {
        dim3 grid(NH / 128, (T_STEPS * BATCH) / 128);
        gemm_xw_kernel<<<grid, 256>>>(inputs, W_xh, b_h, out);
    }

    // t = 0: out[0] = tanh(xw[0])
    tanh0_kernel<<<(int)(step_elems / 4 / 256), 256>>>(out);

    // t = 1..T-1: out[t] = tanh(xw[t] + out[t-1] @ W_hh)
    {
        dim3 grid(NH / 64, BATCH / 32);
        for (int t = 1; t < T_STEPS; t++) {
            rnn_step_kernel<<<grid, 128>>>(out + (size_t)(t - 1) * step_elems,
                                           W_hh,
                                           out + (size_t)t * step_elems);
        }
    }

    // final_state = out[T-1]
    copy_final_kernel<<<(int)(step_elems / 4 / 256), 256>>>(
        out + (size_t)(T_STEPS - 1) * step_elems,
        out + (size_t)T_STEPS * step_elems);
}

// round 3
// speedup vs baseline: 1.9993x; 1.9993x over previous
#include <cuda_runtime.h>
#include <cuda_bf16.h>
#include <math.h>
#include <stdint.h>

// Problem shapes (fixed by reference)
#define T_STEPS 512
#define BATCH   256
#define NIN     1024
#define NH      1024
#define M_TOTAL (T_STEPS * BATCH)   // 131072

// ============================================================================
// Device scratch (static — no allocation allowed)
// ============================================================================
__device__ __nv_bfloat16 g_Ahi[(size_t)M_TOTAL * NIN];   // inputs hi, [M][K]
__device__ __nv_bfloat16 g_Alo[(size_t)M_TOTAL * NIN];   // inputs lo
__device__ __nv_bfloat16 g_Wxh_hi[(size_t)NH * NIN];     // W_xh^T hi, [N][K]
__device__ __nv_bfloat16 g_Wxh_lo[(size_t)NH * NIN];
__device__ __nv_bfloat16 g_Whh_hi[(size_t)NH * NH];      // W_hh^T hi, [N][K]
__device__ __nv_bfloat16 g_Whh_lo[(size_t)NH * NH];
__device__ __nv_bfloat16 g_Hhi[2][(size_t)BATCH * NH];   // state hi, double buffered
__device__ __nv_bfloat16 g_Hlo[2][(size_t)BATCH * NH];

// ============================================================================
// PTX helpers (all sm_80-era: compile for plain compute_103)
// ============================================================================
__device__ __forceinline__ uint32_t smem_u32(const void* p) {
    uint32_t a;
    asm("{ .reg .u64 t; cvta.to.shared.u64 t, %1; cvt.u32.u64 %0, t; }"
        : "=r"(a) : "l"(p));
    return a;
}

#define CP16(dst, src) \
    asm volatile("cp.async.cg.shared.global [%0], [%1], 16;" :: "r"(dst), "l"(src))
#define CP_COMMIT() asm volatile("cp.async.commit_group;" ::: "memory")
#define CP_WAIT(n)  asm volatile("cp.async.wait_group %0;" :: "n"(n) : "memory")

__device__ __forceinline__ void ldsm4(uint32_t r[4], uint32_t addr) {
    asm volatile("ldmatrix.sync.aligned.m8n8.x4.shared.b16 {%0,%1,%2,%3}, [%4];"
                 : "=r"(r[0]), "=r"(r[1]), "=r"(r[2]), "=r"(r[3]) : "r"(addr));
}

__device__ __forceinline__ void mma_bf16(float c[4], const uint32_t a[4],
                                         const uint32_t b[2]) {
    asm volatile(
        "mma.sync.aligned.m16n8k16.row.col.f32.bf16.bf16.f32 "
        "{%0,%1,%2,%3}, {%4,%5,%6,%7}, {%8,%9}, {%0,%1,%2,%3};"
        : "+f"(c[0]), "+f"(c[1]), "+f"(c[2]), "+f"(c[3])
        : "r"(a[0]), "r"(a[1]), "r"(a[2]), "r"(a[3]), "r"(b[0]), "r"(b[1]));
}

// ============================================================================
// Prep: split + transpose a weight [K][N] fp32 -> [N][K] bf16 hi/lo
// which = 0 -> W_xh arrays, 1 -> W_hh arrays
// ============================================================================
__global__ __launch_bounds__(256) void split_w_kernel(const float* __restrict__ W,
                                                      int which)
{
    __shared__ float tile[32][33];
    __nv_bfloat16* hiOut = which ? g_Whh_hi : g_Wxh_hi;
    __nv_bfloat16* loOut = which ? g_Whh_lo : g_Wxh_lo;
    const int bx = blockIdx.x * 32;   // n block
    const int by = blockIdx.y * 32;   // k block
    const int tx = threadIdx.x & 31;
    const int ty = threadIdx.x >> 5;
    for (int i = ty; i < 32; i += 8)
        tile[i][tx] = W[(size_t)(by + i) * NH + bx + tx];
    __syncthreads();
    for (int i = ty; i < 32; i += 8) {
        float x = tile[tx][i];                 // W[by+tx][bx+i]
        __nv_bfloat16 h = __float2bfloat16(x);
        __nv_bfloat16 l = __float2bfloat16(x - __bfloat162float(h));
        size_t o = (size_t)(bx + i) * NIN + by + tx;
        hiOut[o] = h;
        loOut[o] = l;
    }
}

// ============================================================================
// Prep: split inputs fp32 [M][K] -> g_Ahi/g_Alo bf16 (same layout)
// ============================================================================
__global__ __launch_bounds__(256) void split_a_kernel(const float* __restrict__ A)
{
    const size_t n4 = (size_t)M_TOTAL * NIN / 4;
    size_t i = (size_t)blockIdx.x * blockDim.x + threadIdx.x;
    const size_t stride = (size_t)gridDim.x * blockDim.x;
    for (; i < n4; i += stride) {
        float4 v = ((const float4*)A)[i];
        __nv_bfloat16 h0 = __float2bfloat16(v.x);
        __nv_bfloat16 h1 = __float2bfloat16(v.y);
        __nv_bfloat16 h2 = __float2bfloat16(v.z);
        __nv_bfloat16 h3 = __float2bfloat16(v.w);
        __nv_bfloat162 hp0(h0, h1), hp1(h2, h3);
        __nv_bfloat162 lp0(__float2bfloat16(v.x - __bfloat162float(h0)),
                           __float2bfloat16(v.y - __bfloat162float(h1)));
        __nv_bfloat162 lp1(__float2bfloat16(v.z - __bfloat162float(h2)),
                           __float2bfloat16(v.w - __bfloat162float(h3)));
        ((__nv_bfloat162*)g_Ahi)[i * 2 + 0] = hp0;
        ((__nv_bfloat162*)g_Ahi)[i * 2 + 1] = hp1;
        ((__nv_bfloat162*)g_Alo)[i * 2 + 0] = lp0;
        ((__nv_bfloat162*)g_Alo)[i * 2 + 1] = lp1;
    }
}

// ============================================================================
// Phase 1 GEMM: C[M,N] = Ahi/lo @ Whi/lo^T + bias  (split bf16, HMMA)
// CTA 128x128, 256 thr (8 warps 2x4, warp tile 64x32), K-chunk 32, 3 stages.
// smem stage: Ahi[128][40] | Alo | Bhi[128][40] | Blo  (pitch 40 elems = 80B)
// ============================================================================
#define G1_PITCH   40
#define G1_ARR_B   (128 * G1_PITCH * 2)      // 10240 B per array
#define G1_STAGE_B (4 * G1_ARR_B)            // 40960 B per stage
#define G1_SMEM    (3 * G1_STAGE_B)          // 122880 B

__global__ __launch_bounds__(256, 1) void gemm1_kernel(
    const float* __restrict__ bias, float* __restrict__ C)
{
    extern __shared__ char smem[];
    const uint32_t sb0 = smem_u32(smem);
    const int tid  = threadIdx.x;
    const int wid  = tid >> 5;
    const int lane = tid & 31;
    const int m0 = blockIdx.y * 128;
    const int n0 = blockIdx.x * 128;
    const int warp_m = (wid >> 2) * 64;
    const int warp_n = (wid & 3) * 32;

    float acc[4][4][4];
#pragma unroll
    for (int i = 0; i < 4; i++)
#pragma unroll
        for (int j = 0; j < 4; j++)
#pragma unroll
            for (int k = 0; k < 4; k++) acc[i][j][k] = 0.f;

    const int crow = tid >> 2;       // 0..63
    const int cseg = tid & 3;        // 0..3 (16B units)

    // issue cp.async for chunk c into stage s
    auto issue = [&](int c, int s) {
        const uint32_t st = sb0 + s * G1_STAGE_B;
        const int kb = c * 32 + cseg * 8;            // element offset in K
#pragma unroll
        for (int h = 0; h < 2; h++) {
            const int r = crow + h * 64;
            const size_t ga = (size_t)(m0 + r) * NIN + kb;
            const size_t gb = (size_t)(n0 + r) * NIN + kb;
            const uint32_t so = r * 80 + cseg * 16;
            CP16(st + so,                  g_Ahi + ga);
            CP16(st + G1_ARR_B + so,       g_Alo + ga);
            CP16(st + 2 * G1_ARR_B + so,   g_Wxh_hi + gb);
            CP16(st + 3 * G1_ARR_B + so,   g_Wxh_lo + gb);
        }
    };

    issue(0, 0); CP_COMMIT();
    issue(1, 1); CP_COMMIT();

    for (int it = 0; it < 32; it++) {
        CP_WAIT(1);
        __syncthreads();
        if (it + 2 < 32) issue(it + 2, (it + 2) % 3);
        CP_COMMIT();

        const uint32_t st = sb0 + (it % 3) * G1_STAGE_B;
#pragma unroll
        for (int ks = 0; ks < 2; ks++) {
            const uint32_t kb = ks * 32;   // byte offset of k16 step
            uint32_t ah[4][4], al[4][4];
#pragma unroll
            for (int mt = 0; mt < 4; mt++) {
                const int mr = warp_m + mt * 16 + (lane & 15);
                const uint32_t ad = st + mr * 80 + ((lane >> 4) * 16) + kb;
                ldsm4(ah[mt], ad);
                ldsm4(al[mt], ad + G1_ARR_B);
            }
            uint32_t bh[4][2], bl[4][2];
#pragma unroll
            for (int g = 0; g < 2; g++) {
                const int nr = warp_n + g * 16 + (lane & 7) + ((lane >> 4) << 3);
                const uint32_t bd = st + 2 * G1_ARR_B + nr * 80 +
                                    (((lane >> 3) & 1) * 16) + kb;
                uint32_t t[4];
                ldsm4(t, bd);
                bh[g * 2][0] = t[0]; bh[g * 2][1] = t[1];
                bh[g * 2 + 1][0] = t[2]; bh[g * 2 + 1][1] = t[3];
                ldsm4(t, bd + G1_ARR_B);
                bl[g * 2][0] = t[0]; bl[g * 2][1] = t[1];
                bl[g * 2 + 1][0] = t[2]; bl[g * 2 + 1][1] = t[3];
            }
#pragma unroll
            for (int mt = 0; mt < 4; mt++)
#pragma unroll
                for (int nt = 0; nt < 4; nt++) {
                    mma_bf16(acc[mt][nt], ah[mt], bh[nt]);   // hi*hi
                    mma_bf16(acc[mt][nt], ah[mt], bl[nt]);   // hi*lo
                    mma_bf16(acc[mt][nt], al[mt], bh[nt]);   // lo*hi
                }
        }
    }

    // Epilogue: add bias, write C
#pragma unroll
    for (int mt = 0; mt < 4; mt++) {
        const int m = m0 + warp_m + mt * 16 + (lane >> 2);
#pragma unroll
        for (int nt = 0; nt < 4; nt++) {
            const int n = n0 + warp_n + nt * 8 + (lane & 3) * 2;
            const float b0 = bias[n], b1 = bias[n + 1];
            float2 v0 = make_float2(acc[mt][nt][0] + b0, acc[mt][nt][1] + b1);
            float2 v1 = make_float2(acc[mt][nt][2] + b0, acc[mt][nt][3] + b1);
            *(float2*)(C + (size_t)m * NH + n)       = v0;
            *(float2*)(C + (size_t)(m + 8) * NH + n) = v1;
        }
    }
}

// ============================================================================
// t = 0: h0 = tanh(xw[0]); write fp32 out[0] and bf16 hi/lo state buf 0
// ============================================================================
__global__ __launch_bounds__(256) void tanh0_kernel(float* __restrict__ x)
{
    const size_t i = (size_t)blockIdx.x * blockDim.x + threadIdx.x;  // float4 idx
    float4 v = ((const float4*)x)[i];
    v.x = tanhf(v.x); v.y = tanhf(v.y); v.z = tanhf(v.z); v.w = tanhf(v.w);
    ((float4*)x)[i] = v;
    __nv_bfloat16 h0 = __float2bfloat16(v.x);
    __nv_bfloat16 h1 = __float2bfloat16(v.y);
    __nv_bfloat16 h2 = __float2bfloat16(v.z);
    __nv_bfloat16 h3 = __float2bfloat16(v.w);
    ((__nv_bfloat162*)g_Hhi[0])[i * 2 + 0] = __nv_bfloat162(h0, h1);
    ((__nv_bfloat162*)g_Hhi[0])[i * 2 + 1] = __nv_bfloat162(h2, h3);
    ((__nv_bfloat162*)g_Hlo[0])[i * 2 + 0] =
        __nv_bfloat162(__float2bfloat16(v.x - __bfloat162float(h0)),
                       __float2bfloat16(v.y - __bfloat162float(h1)));
    ((__nv_bfloat162*)g_Hlo[0])[i * 2 + 1] =
        __nv_bfloat162(__float2bfloat16(v.z - __bfloat162float(h2)),
                       __float2bfloat16(v.w - __bfloat162float(h3)));
}

// ============================================================================
// RNN step (HMMA split bf16):
//   out[t] = tanh(xw[t] + h_{t-1} @ W_hh), also emits bf16 hi/lo of h_t.
// CTA 32x64, 128 thr (4 warps 2x2, warp tile 16x32), K-chunk 32, 4 stages.
// smem stage: Ahi[32][40] | Alo | Bhi[64][40] | Blo
// ============================================================================
#define G2_PITCH   40
#define G2_A_B     (32 * G2_PITCH * 2)       // 2560 B
#define G2_B_B     (64 * G2_PITCH * 2)       // 5120 B
#define G2_STAGE_B (2 * G2_A_B + 2 * G2_B_B) // 15360 B
#define G2_SMEM    (4 * G2_STAGE_B)          // 61440 B

__global__ __launch_bounds__(128, 1) void rnn_step_kernel(
    const float* __restrict__ XW,   // xw[t] (read)
    float* __restrict__ OUT,        // out[t] (write)
    int rb)                         // read H buffer index; writes rb^1
{
    extern __shared__ char smem[];
    const uint32_t sb0 = smem_u32(smem);
    const int tid  = threadIdx.x;
    const int wid  = tid >> 5;
    const int lane = tid & 31;
    const int m0 = blockIdx.y * 32;
    const int n0 = blockIdx.x * 64;
    const int warp_m = (wid >> 1) * 16;
    const int warp_n = (wid & 1) * 32;

    const __nv_bfloat16* Hhi = g_Hhi[rb];
    const __nv_bfloat16* Hlo = g_Hlo[rb];
    __nv_bfloat16* HhiO = g_Hhi[rb ^ 1];
    __nv_bfloat16* HloO = g_Hlo[rb ^ 1];

    float acc[4][4];
#pragma unroll
    for (int i = 0; i < 4; i++)
#pragma unroll
        for (int k = 0; k < 4; k++) acc[i][k] = 0.f;

    const int crow = tid >> 2;    // 0..31
    const int cseg = tid & 3;

    auto issue = [&](int c, int s) {
        const uint32_t st = sb0 + s * G2_STAGE_B;
        const int kb = c * 32 + cseg * 8;
        {
            const size_t ga = (size_t)(m0 + crow) * NH + kb;
            const uint32_t so = crow * 80 + cseg * 16;
            CP16(st + so,          Hhi + ga);
            CP16(st + G2_A_B + so, Hlo + ga);
        }
#pragma unroll
        for (int h = 0; h < 2; h++) {
            const int r = crow + h * 32;
            const size_t gb = (size_t)(n0 + r) * NH + kb;
            const uint32_t so = r * 80 + cseg * 16;
            CP16(st + 2 * G2_A_B + so,          g_Whh_hi + gb);
            CP16(st + 2 * G2_A_B + G2_B_B + so, g_Whh_lo + gb);
        }
    };

    issue(0, 0); CP_COMMIT();
    issue(1, 1); CP_COMMIT();
    issue(2, 2); CP_COMMIT();

    for (int it = 0; it < 32; it++) {
        CP_WAIT(2);
        __syncthreads();
        if (it + 3 < 32) issue(it + 3, (it + 3) & 3);
        CP_COMMIT();

        const uint32_t st = sb0 + (it & 3) * G2_STAGE_B;
#pragma unroll
        for (int ks = 0; ks < 2; ks++) {
            const uint32_t kb = ks * 32;
            uint32_t ah[4], al[4];
            {
                const int mr = warp_m + (lane & 15);
                const uint32_t ad = st + mr * 80 + ((lane >> 4) * 16) + kb;
                ldsm4(ah, ad);
                ldsm4(al, ad + G2_A_B);
            }
            uint32_t bh[4][2], bl[4][2];
#pragma unroll
            for (int g = 0; g < 2; g++) {
                const int nr = warp_n + g * 16 + (lane & 7) + ((lane >> 4) << 3);
                const uint32_t bd = st + 2 * G2_A_B + nr * 80 +
                                    (((lane >> 3) & 1) * 16) + kb;
                uint32_t t[4];
                ldsm4(t, bd);
                bh[g * 2][0] = t[0]; bh[g * 2][1] = t[1];
                bh[g * 2 + 1][0] = t[2]; bh[g * 2 + 1][1] = t[3];
                ldsm4(t, bd + G2_B_B);
                bl[g * 2][0] = t[0]; bl[g * 2][1] = t[1];
                bl[g * 2 + 1][0] = t[2]; bl[g * 2 + 1][1] = t[3];
            }
#pragma unroll
            for (int nt = 0; nt < 4; nt++) {
                mma_bf16(acc[nt], ah, bh[nt]);
                mma_bf16(acc[nt], ah, bl[nt]);
                mma_bf16(acc[nt], al, bh[nt]);
            }
        }
    }

    // Epilogue: h = tanh(xw + acc); write fp32 OUT + bf16 hi/lo state
    const int mrow = m0 + warp_m + (lane >> 2);
#pragma unroll
    for (int half = 0; half < 2; half++) {
        const int m = mrow + half * 8;
#pragma unroll
        for (int nt = 0; nt < 4; nt++) {
            const int n = n0 + warp_n + nt * 8 + (lane & 3) * 2;
            const size_t off = (size_t)m * NH + n;
            float2 xw = *(const float2*)(XW + off);
            float v0 = tanhf(xw.x + acc[nt][half * 2 + 0]);
            float v1 = tanhf(xw.y + acc[nt][half * 2 + 1]);
            *(float2*)(OUT + off) = make_float2(v0, v1);
            __nv_bfloat16 h0 = __float2bfloat16(v0);
            __nv_bfloat16 h1 = __float2bfloat16(v1);
            *(__nv_bfloat162*)(HhiO + off) = __nv_bfloat162(h0, h1);
            *(__nv_bfloat162*)(HloO + off) =
                __nv_bfloat162(__float2bfloat16(v0 - __bfloat162float(h0)),
                               __float2bfloat16(v1 - __bfloat162float(h1)));
        }
    }
}

// ============================================================================
// Copy final state (= out[T-1]) to the tail of the output buffer.
// ============================================================================
__global__ void copy_final_kernel(const float* __restrict__ src,
                                  float* __restrict__ dst)
{
    int idx = blockIdx.x * blockDim.x + threadIdx.x;
    ((float4*)dst)[idx] = ((const float4*)src)[idx];
}

// ============================================================================
// Launch
// ============================================================================
extern "C" void kernel_launch(void* const* d_in, const int* in_sizes, int n_in,
                              void* d_out, int out_size)
{
    const float* inputs = (const float*)d_in[0];   // [T, B, NIN]
    const float* W_xh   = (const float*)d_in[1];   // [NIN, NH]
    const float* W_hh   = (const float*)d_in[2];   // [NH, NH]
    const float* b_h    = (const float*)d_in[3];   // [NH]
    float* out = (float*)d_out;                    // [T, B, NH] + [B, NH]

    const size_t step_elems = (size_t)BATCH * NH;  // 262144

    static bool attr_set = false;
    if (!attr_set) {
        cudaFuncSetAttribute(gemm1_kernel,
                             cudaFuncAttributeMaxDynamicSharedMemorySize, G1_SMEM);
        cudaFuncSetAttribute(rnn_step_kernel,
                             cudaFuncAttributeMaxDynamicSharedMemorySize, G2_SMEM);
        attr_set = true;
    }

    // Prep: split weights (transposed) and inputs into bf16 hi/lo
    {
        dim3 grid(NH / 32, NIN / 32);
        split_w_kernel<<<grid, 256>>>(W_xh, 0);
        split_w_kernel<<<grid, 256>>>(W_hh, 1);
        split_a_kernel<<<8192, 256>>>(inputs);
    }

    // Phase 1: xw = inputs @ W_xh + b_h  -> out[0..T)
    {
        dim3 grid(NH / 128, M_TOTAL / 128);   // (8, 1024)
        gemm1_kernel<<<grid, 256, G1_SMEM>>>(b_h, out);
    }

    // t = 0
    tanh0_kernel<<<(int)(step_elems / 4 / 256), 256>>>(out);

    // t = 1..T-1
    {
        dim3 grid(NH / 64, BATCH / 32);       // (16, 8) = 128 CTAs
        for (int t = 1; t < T_STEPS; t++) {
            rnn_step_kernel<<<grid, 128, G2_SMEM>>>(
                out + (size_t)t * step_elems,        // XW read
                out + (size_t)t * step_elems,        // OUT write (in place)
                (t - 1) & 1);
        }
    }

    // final_state = out[T-1]
    copy_final_kernel<<<(int)(step_elems / 4 / 256), 256>>>(
        out + (size_t)(T_STEPS - 1) * step_elems,
        out + (size_t)T_STEPS * step_elems);
}

// round 4
// speedup vs baseline: 2.3198x; 1.1603x over previous
#include <cuda_runtime.h>
#include <cuda_bf16.h>
#include <math.h>
#include <stdint.h>

// Problem shapes (fixed by reference)
#define T_STEPS 512
#define BATCH   256
#define NIN     1024
#define NH      1024
#define M_TOTAL (T_STEPS * BATCH)   // 131072

// ============================================================================
// Device scratch (static — no allocation allowed)
// ============================================================================
__device__ __nv_bfloat16 g_Ahi[(size_t)M_TOTAL * NIN];   // inputs hi, [M][K]
__device__ __nv_bfloat16 g_Alo[(size_t)M_TOTAL * NIN];   // inputs lo
__device__ __nv_bfloat16 g_Wxh_hi[(size_t)NH * NIN];     // W_xh^T hi, [N][K]
__device__ __nv_bfloat16 g_Wxh_lo[(size_t)NH * NIN];
__device__ __nv_bfloat16 g_Whh_hi[(size_t)NH * NH];      // W_hh^T hi, [N][K]
__device__ __nv_bfloat16 g_Whh_lo[(size_t)NH * NH];
__device__ __nv_bfloat16 g_Hhi[2][(size_t)BATCH * NH];   // state hi, double buffered
__device__ __nv_bfloat16 g_Hlo[2][(size_t)BATCH * NH];

// Grid barrier state (zero-initialized; count self-resets, phase is monotonic)
__device__ unsigned g_bar_count;
__device__ unsigned g_bar_phase;

// ============================================================================
// PTX helpers (all sm_80-era: compile for plain compute_103)
// ============================================================================
__device__ __forceinline__ uint32_t smem_u32(const void* p) {
    uint32_t a;
    asm("{ .reg .u64 t; cvta.to.shared.u64 t, %1; cvt.u32.u64 %0, t; }"
        : "=r"(a) : "l"(p));
    return a;
}

#define CP16(dst, src) \
    asm volatile("cp.async.cg.shared.global [%0], [%1], 16;" :: "r"(dst), "l"(src))
#define CP_COMMIT() asm volatile("cp.async.commit_group;" ::: "memory")
#define CP_WAIT(n)  asm volatile("cp.async.wait_group %0;" :: "n"(n) : "memory")

__device__ __forceinline__ void ldsm4(uint32_t r[4], uint32_t addr) {
    asm volatile("ldmatrix.sync.aligned.m8n8.x4.shared.b16 {%0,%1,%2,%3}, [%4];"
                 : "=r"(r[0]), "=r"(r[1]), "=r"(r[2]), "=r"(r[3]) : "r"(addr));
}

__device__ __forceinline__ void mma_bf16(float c[4], const uint32_t a[4],
                                         const uint32_t b[2]) {
    asm volatile(
        "mma.sync.aligned.m16n8k16.row.col.f32.bf16.bf16.f32 "
        "{%0,%1,%2,%3}, {%4,%5,%6,%7}, {%8,%9}, {%0,%1,%2,%3};"
        : "+f"(c[0]), "+f"(c[1]), "+f"(c[2]), "+f"(c[3])
        : "r"(a[0]), "r"(a[1]), "r"(a[2]), "r"(a[3]), "r"(b[0]), "r"(b[1]));
}

__device__ __forceinline__ unsigned ld_acq(unsigned* p) {
    unsigned v;
    asm volatile("ld.acquire.gpu.global.u32 %0, [%1];" : "=r"(v) : "l"(p) : "memory");
    return v;
}
__device__ __forceinline__ void st_rel(unsigned* p, unsigned v) {
    asm volatile("st.release.gpu.global.u32 [%0], %1;" :: "l"(p), "r"(v) : "memory");
}

#define PK_CTAS 128

// Called by thread 0 of every CTA. All PK_CTAS CTAs are co-resident.
__device__ __forceinline__ void grid_bar() {
    unsigned ph = ld_acq(&g_bar_phase);
    __threadfence();
    unsigned old = atomicAdd(&g_bar_count, 1);
    if (old == PK_CTAS - 1) {
        g_bar_count = 0;
        st_rel(&g_bar_phase, ph + 1);
    } else {
        while (ld_acq(&g_bar_phase) == ph) { }
    }
}

// ============================================================================
// Prep: split + transpose a weight [K][N] fp32 -> [N][K] bf16 hi/lo
// ============================================================================
__global__ __launch_bounds__(256) void split_w_kernel(const float* __restrict__ W,
                                                      int which)
{
    __shared__ float tile[32][33];
    __nv_bfloat16* hiOut = which ? g_Whh_hi : g_Wxh_hi;
    __nv_bfloat16* loOut = which ? g_Whh_lo : g_Wxh_lo;
    const int bx = blockIdx.x * 32;   // n block
    const int by = blockIdx.y * 32;   // k block
    const int tx = threadIdx.x & 31;
    const int ty = threadIdx.x >> 5;
    for (int i = ty; i < 32; i += 8)
        tile[i][tx] = W[(size_t)(by + i) * NH + bx + tx];
    __syncthreads();
    for (int i = ty; i < 32; i += 8) {
        float x = tile[tx][i];                 // W[by+tx][bx+i]
        __nv_bfloat16 h = __float2bfloat16(x);
        __nv_bfloat16 l = __float2bfloat16(x - __bfloat162float(h));
        size_t o = (size_t)(bx + i) * NIN + by + tx;
        hiOut[o] = h;
        loOut[o] = l;
    }
}

// ============================================================================
// Prep: split inputs fp32 [M][K] -> g_Ahi/g_Alo bf16 (same layout)
// ============================================================================
__global__ __launch_bounds__(256) void split_a_kernel(const float* __restrict__ A)
{
    const size_t n4 = (size_t)M_TOTAL * NIN / 4;
    size_t i = (size_t)blockIdx.x * blockDim.x + threadIdx.x;
    const size_t stride = (size_t)gridDim.x * blockDim.x;
    for (; i < n4; i += stride) {
        float4 v = ((const float4*)A)[i];
        __nv_bfloat16 h0 = __float2bfloat16(v.x);
        __nv_bfloat16 h1 = __float2bfloat16(v.y);
        __nv_bfloat16 h2 = __float2bfloat16(v.z);
        __nv_bfloat16 h3 = __float2bfloat16(v.w);
        __nv_bfloat162 hp0(h0, h1), hp1(h2, h3);
        __nv_bfloat162 lp0(__float2bfloat16(v.x - __bfloat162float(h0)),
                           __float2bfloat16(v.y - __bfloat162float(h1)));
        __nv_bfloat162 lp1(__float2bfloat16(v.z - __bfloat162float(h2)),
                           __float2bfloat16(v.w - __bfloat162float(h3)));
        ((__nv_bfloat162*)g_Ahi)[i * 2 + 0] = hp0;
        ((__nv_bfloat162*)g_Ahi)[i * 2 + 1] = hp1;
        ((__nv_bfloat162*)g_Alo)[i * 2 + 0] = lp0;
        ((__nv_bfloat162*)g_Alo)[i * 2 + 1] = lp1;
    }
}

// ============================================================================
// Phase 1 GEMM: C[M,N] = Ahi/lo @ Whi/lo^T + bias  (split bf16, HMMA)
// CTA 128x128, 256 thr (8 warps 2x4, warp tile 64x32), K-chunk 32, 3 stages.
// ============================================================================
#define G1_PITCH   40
#define G1_ARR_B   (128 * G1_PITCH * 2)      // 10240 B per array
#define G1_STAGE_B (4 * G1_ARR_B)            // 40960 B per stage
#define G1_SMEM    (3 * G1_STAGE_B)          // 122880 B

__global__ __launch_bounds__(256, 1) void gemm1_kernel(
    const float* __restrict__ bias, float* __restrict__ C)
{
    extern __shared__ char smem[];
    const uint32_t sb0 = smem_u32(smem);
    const int tid  = threadIdx.x;
    const int wid  = tid >> 5;
    const int lane = tid & 31;
    const int m0 = blockIdx.y * 128;
    const int n0 = blockIdx.x * 128;
    const int warp_m = (wid >> 2) * 64;
    const int warp_n = (wid & 3) * 32;

    float acc[4][4][4];
#pragma unroll
    for (int i = 0; i < 4; i++)
#pragma unroll
        for (int j = 0; j < 4; j++)
#pragma unroll
            for (int k = 0; k < 4; k++) acc[i][j][k] = 0.f;

    const int crow = tid >> 2;       // 0..63
    const int cseg = tid & 3;        // 0..3 (16B units)

    auto issue = [&](int c, int s) {
        const uint32_t st = sb0 + s * G1_STAGE_B;
        const int kb = c * 32 + cseg * 8;
#pragma unroll
        for (int h = 0; h < 2; h++) {
            const int r = crow + h * 64;
            const size_t ga = (size_t)(m0 + r) * NIN + kb;
            const size_t gb = (size_t)(n0 + r) * NIN + kb;
            const uint32_t so = r * 80 + cseg * 16;
            CP16(st + so,                  g_Ahi + ga);
            CP16(st + G1_ARR_B + so,       g_Alo + ga);
            CP16(st + 2 * G1_ARR_B + so,   g_Wxh_hi + gb);
            CP16(st + 3 * G1_ARR_B + so,   g_Wxh_lo + gb);
        }
    };

    issue(0, 0); CP_COMMIT();
    issue(1, 1); CP_COMMIT();

    for (int it = 0; it < 32; it++) {
        CP_WAIT(1);
        __syncthreads();
        if (it + 2 < 32) issue(it + 2, (it + 2) % 3);
        CP_COMMIT();

        const uint32_t st = sb0 + (it % 3) * G1_STAGE_B;
#pragma unroll
        for (int ks = 0; ks < 2; ks++) {
            const uint32_t kb = ks * 32;
            uint32_t ah[4][4], al[4][4];
#pragma unroll
            for (int mt = 0; mt < 4; mt++) {
                const int mr = warp_m + mt * 16 + (lane & 15);
                const uint32_t ad = st + mr * 80 + ((lane >> 4) * 16) + kb;
                ldsm4(ah[mt], ad);
                ldsm4(al[mt], ad + G1_ARR_B);
            }
            uint32_t bh[4][2], bl[4][2];
#pragma unroll
            for (int g = 0; g < 2; g++) {
                const int nr = warp_n + g * 16 + (lane & 7) + ((lane >> 4) << 3);
                const uint32_t bd = st + 2 * G1_ARR_B + nr * 80 +
                                    (((lane >> 3) & 1) * 16) + kb;
                uint32_t t[4];
                ldsm4(t, bd);
                bh[g * 2][0] = t[0]; bh[g * 2][1] = t[1];
                bh[g * 2 + 1][0] = t[2]; bh[g * 2 + 1][1] = t[3];
                ldsm4(t, bd + G1_ARR_B);
                bl[g * 2][0] = t[0]; bl[g * 2][1] = t[1];
                bl[g * 2 + 1][0] = t[2]; bl[g * 2 + 1][1] = t[3];
            }
#pragma unroll
            for (int mt = 0; mt < 4; mt++)
#pragma unroll
                for (int nt = 0; nt < 4; nt++) {
                    mma_bf16(acc[mt][nt], ah[mt], bh[nt]);
                    mma_bf16(acc[mt][nt], ah[mt], bl[nt]);
                    mma_bf16(acc[mt][nt], al[mt], bh[nt]);
                }
        }
    }

#pragma unroll
    for (int mt = 0; mt < 4; mt++) {
        const int m = m0 + warp_m + mt * 16 + (lane >> 2);
#pragma unroll
        for (int nt = 0; nt < 4; nt++) {
            const int n = n0 + warp_n + nt * 8 + (lane & 3) * 2;
            const float b0 = bias[n], b1 = bias[n + 1];
            float2 v0 = make_float2(acc[mt][nt][0] + b0, acc[mt][nt][1] + b1);
            float2 v1 = make_float2(acc[mt][nt][2] + b0, acc[mt][nt][3] + b1);
            *(float2*)(C + (size_t)m * NH + n)       = v0;
            *(float2*)(C + (size_t)(m + 8) * NH + n) = v1;
        }
    }
}

// ============================================================================
// t = 0: h0 = tanh(xw[0]); write fp32 out[0] and bf16 hi/lo state buf 0
// ============================================================================
__global__ __launch_bounds__(256) void tanh0_kernel(float* __restrict__ x)
{
    const size_t i = (size_t)blockIdx.x * blockDim.x + threadIdx.x;  // float4 idx
    float4 v = ((const float4*)x)[i];
    v.x = tanhf(v.x); v.y = tanhf(v.y); v.z = tanhf(v.z); v.w = tanhf(v.w);
    ((float4*)x)[i] = v;
    __nv_bfloat16 h0 = __float2bfloat16(v.x);
    __nv_bfloat16 h1 = __float2bfloat16(v.y);
    __nv_bfloat16 h2 = __float2bfloat16(v.z);
    __nv_bfloat16 h3 = __float2bfloat16(v.w);
    ((__nv_bfloat162*)g_Hhi[0])[i * 2 + 0] = __nv_bfloat162(h0, h1);
    ((__nv_bfloat162*)g_Hhi[0])[i * 2 + 1] = __nv_bfloat162(h2, h3);
    ((__nv_bfloat162*)g_Hlo[0])[i * 2 + 0] =
        __nv_bfloat162(__float2bfloat16(v.x - __bfloat162float(h0)),
                       __float2bfloat16(v.y - __bfloat162float(h1)));
    ((__nv_bfloat162*)g_Hlo[0])[i * 2 + 1] =
        __nv_bfloat162(__float2bfloat16(v.z - __bfloat162float(h2)),
                       __float2bfloat16(v.w - __bfloat162float(h3)));
}

// ============================================================================
// Persistent RNN recurrence kernel: runs t = 1..511 with a grid barrier.
// 128 CTAs = 4 m-blocks (64 rows) x 32 n-blocks (32 cols), 256 threads.
// W_hh hi+lo slice for this CTA's 32 n-rows stays RESIDENT in smem (160 KB);
// H hi/lo streamed per step via 4-stage cp.async pipeline.
// smem layout:
//   [0, 81920)        W hi resident: 32 chunks x 32 rows x 80 B
//   [81920, 163840)   W lo resident
//   [163840, 204800)  H stages: 4 x { hi [64][80B], lo at +5120 }
// ============================================================================
#define PW_HI    0
#define PW_LO    81920
#define PH_BASE  163840
#define PH_STAGE 10240
#define PH_LO    5120
#define PK_SMEM  204800

__global__ __launch_bounds__(256, 1) void rnn_persist_kernel(float* __restrict__ out)
{
    extern __shared__ char smem[];
    const uint32_t sb = smem_u32(smem);
    const int tid  = threadIdx.x;
    const int wid  = tid >> 5;
    const int lane = tid & 31;
    const int mb = blockIdx.x >> 5;    // 0..3
    const int nb = blockIdx.x & 31;    // 0..31
    const int m0 = mb * 64;
    const int n0 = nb * 32;
    const int warp_m = (wid >> 1) * 16;   // 0..48
    const int warp_n = (wid & 1) * 16;    // 0 or 16

    // ---- Load resident W_hh slice (hi+lo), chunked K-major, pitch 80B ----
    for (int idx = tid; idx < 4096; idx += 256) {
        const int ch  = idx >> 7;          // 0..31  k-chunk
        const int r   = (idx >> 2) & 31;   // 0..31  n-row
        const int seg = idx & 3;           // 0..3   16B seg
        const size_t g = (size_t)(n0 + r) * NH + ch * 32 + seg * 8;
        const uint32_t so = sb + ch * 2560 + r * 80 + seg * 16;
        CP16(so + PW_HI, g_Whh_hi + g);
        CP16(so + PW_LO, g_Whh_lo + g);
    }
    CP_COMMIT(); CP_WAIT(0); __syncthreads();

    const int hrow = tid >> 2;   // 0..63
    const int hseg = tid & 3;

    for (int t = 1; t < T_STEPS; t++) {
        const __nv_bfloat16* Hh = g_Hhi[(t - 1) & 1];
        const __nv_bfloat16* Hl = g_Hlo[(t - 1) & 1];
        __nv_bfloat16* HhO = g_Hhi[t & 1];
        __nv_bfloat16* HlO = g_Hlo[t & 1];
        float* X = out + (size_t)t * BATCH * NH;

        // Prefetch this CTA's xw tile into registers (independent of barrier)
        float2 xwr[2][2];
        {
            const int mrow = m0 + warp_m + (lane >> 2);
#pragma unroll
            for (int half = 0; half < 2; half++)
#pragma unroll
                for (int nt = 0; nt < 2; nt++) {
                    const int m = mrow + half * 8;
                    const int n = n0 + warp_n + nt * 8 + (lane & 3) * 2;
                    xwr[half][nt] = *(const float2*)(X + (size_t)m * NH + n);
                }
        }

        auto issueH = [&](int c, int s) {
            const uint32_t st = sb + PH_BASE + s * PH_STAGE + hrow * 80 + hseg * 16;
            const size_t ga = (size_t)(m0 + hrow) * NH + c * 32 + hseg * 8;
            CP16(st, Hh + ga);
            CP16(st + PH_LO, Hl + ga);
        };
        issueH(0, 0); CP_COMMIT();
        issueH(1, 1); CP_COMMIT();
        issueH(2, 2); CP_COMMIT();

        float acc[2][4];
#pragma unroll
        for (int i = 0; i < 2; i++)
#pragma unroll
            for (int j = 0; j < 4; j++) acc[i][j] = 0.f;

        for (int it = 0; it < 32; it++) {
            CP_WAIT(2);
            __syncthreads();
            if (it + 3 < 32) issueH(it + 3, (it + 3) & 3);
            CP_COMMIT();

            const uint32_t hst = sb + PH_BASE + (it & 3) * PH_STAGE;
            const uint32_t wch = sb + it * 2560;
#pragma unroll
            for (int ks = 0; ks < 2; ks++) {
                const uint32_t kb = ks * 32;
                uint32_t ah[4], al[4];
                {
                    const uint32_t ad = hst + (warp_m + (lane & 15)) * 80 +
                                        ((lane >> 4) * 16) + kb;
                    ldsm4(ah, ad);
                    ldsm4(al, ad + PH_LO);
                }
                uint32_t bh[2][2], bl[2][2];
                {
                    const int nr = warp_n + (lane & 7) + ((lane >> 4) << 3);
                    const uint32_t bd = wch + nr * 80 +
                                        (((lane >> 3) & 1) * 16) + kb;
                    uint32_t tmp[4];
                    ldsm4(tmp, bd + PW_HI);
                    bh[0][0] = tmp[0]; bh[0][1] = tmp[1];
                    bh[1][0] = tmp[2]; bh[1][1] = tmp[3];
                    ldsm4(tmp, bd + PW_LO);
                    bl[0][0] = tmp[0]; bl[0][1] = tmp[1];
                    bl[1][0] = tmp[2]; bl[1][1] = tmp[3];
                }
#pragma unroll
                for (int nt = 0; nt < 2; nt++) {
                    mma_bf16(acc[nt], ah, bh[nt]);
                    mma_bf16(acc[nt], ah, bl[nt]);
                    mma_bf16(acc[nt], al, bh[nt]);
                }
            }
        }
        __syncthreads();   // all warps done with H stages before next step reuses

        // ---- Epilogue: h = tanh(xw + acc); write out + bf16 hi/lo state ----
        {
            const int mrow = m0 + warp_m + (lane >> 2);
#pragma unroll
            for (int half = 0; half < 2; half++) {
                const int m = mrow + half * 8;
#pragma unroll
                for (int nt = 0; nt < 2; nt++) {
                    const int n = n0 + warp_n + nt * 8 + (lane & 3) * 2;
                    const size_t off = (size_t)m * NH + n;
                    const float v0 = tanhf(xwr[half][nt].x + acc[nt][half * 2 + 0]);
                    const float v1 = tanhf(xwr[half][nt].y + acc[nt][half * 2 + 1]);
                    *(float2*)(X + off) = make_float2(v0, v1);
                    const __nv_bfloat16 h0 = __float2bfloat16(v0);
                    const __nv_bfloat16 h1 = __float2bfloat16(v1);
                    *(__nv_bfloat162*)(HhO + off) = __nv_bfloat162(h0, h1);
                    *(__nv_bfloat162*)(HlO + off) = __nv_bfloat162(
                        __float2bfloat16(v0 - __bfloat162float(h0)),
                        __float2bfloat16(v1 - __bfloat162float(h1)));
                    if (t == T_STEPS - 1)
                        *(float2*)(out + (size_t)T_STEPS * BATCH * NH + off) =
                            make_float2(v0, v1);
                }
            }
        }

        // ---- Grid barrier between steps ----
        __syncthreads();
        if (tid == 0) grid_bar();
        __syncthreads();
    }
}

// ============================================================================
// Launch
// ============================================================================
extern "C" void kernel_launch(void* const* d_in, const int* in_sizes, int n_in,
                              void* d_out, int out_size)
{
    const float* inputs = (const float*)d_in[0];   // [T, B, NIN]
    const float* W_xh   = (const float*)d_in[1];   // [NIN, NH]
    const float* W_hh   = (const float*)d_in[2];   // [NH, NH]
    const float* b_h    = (const float*)d_in[3];   // [NH]
    float* out = (float*)d_out;                    // [T, B, NH] + [B, NH]

    const size_t step_elems = (size_t)BATCH * NH;  // 262144

    static bool attr_set = false;
    if (!attr_set) {
        cudaFuncSetAttribute(gemm1_kernel,
                             cudaFuncAttributeMaxDynamicSharedMemorySize, G1_SMEM);
        cudaFuncSetAttribute(rnn_persist_kernel,
                             cudaFuncAttributeMaxDynamicSharedMemorySize, PK_SMEM);
        attr_set = true;
    }

    // Prep: split weights (transposed) and inputs into bf16 hi/lo
    {
        dim3 grid(NH / 32, NIN / 32);
        split_w_kernel<<<grid, 256>>>(W_xh, 0);
        split_w_kernel<<<grid, 256>>>(W_hh, 1);
        split_a_kernel<<<8192, 256>>>(inputs);
    }

    // Phase 1: xw = inputs @ W_xh + b_h  -> out[0..T)
    {
        dim3 grid(NH / 128, M_TOTAL / 128);   // (8, 1024)
        gemm1_kernel<<<grid, 256, G1_SMEM>>>(b_h, out);
    }

    // t = 0
    tanh0_kernel<<<(int)(step_elems / 4 / 256), 256>>>(out);

    // t = 1..T-1 in ONE persistent kernel (also writes final_state tail)
    rnn_persist_kernel<<<PK_CTAS, 256, PK_SMEM>>>(out);
}

// round 5
// speedup vs baseline: 2.3373x; 1.0076x over previous
#include <cuda_runtime.h>
#include <cuda_bf16.h>
#include <math.h>
#include <stdint.h>

// Problem shapes (fixed by reference)
#define T_STEPS 512
#define BATCH   256
#define NIN     1024
#define NH      1024
#define M_TOTAL (T_STEPS * BATCH)   // 131072

// ============================================================================
// Device scratch (static — no allocation allowed)
// ============================================================================
__device__ __nv_bfloat16 g_Ahi[(size_t)M_TOTAL * NIN];   // inputs hi, [M][K]
__device__ __nv_bfloat16 g_Alo[(size_t)M_TOTAL * NIN];   // inputs lo
__device__ __nv_bfloat16 g_Wxh_hi[(size_t)NH * NIN];     // W_xh^T hi, [N][K]
__device__ __nv_bfloat16 g_Wxh_lo[(size_t)NH * NIN];
__device__ __nv_bfloat16 g_Whh_hi[(size_t)NH * NH];      // W_hh^T hi, [N][K]
__device__ __nv_bfloat16 g_Whh_lo[(size_t)NH * NH];
__device__ __nv_bfloat16 g_Hhi[2][(size_t)BATCH * NH];   // state hi, double buffered
__device__ __nv_bfloat16 g_Hlo[2][(size_t)BATCH * NH];

// Per-m-group barrier state (4 groups of 32 CTAs); zero-init, phase monotonic
__device__ unsigned g_bar_count[4];
__device__ unsigned g_bar_phase[4];

// ============================================================================
// PTX helpers (all sm_80-era: compile for plain compute_103)
// ============================================================================
__device__ __forceinline__ uint32_t smem_u32(const void* p) {
    uint32_t a;
    asm("{ .reg .u64 t; cvta.to.shared.u64 t, %1; cvt.u32.u64 %0, t; }"
        : "=r"(a) : "l"(p));
    return a;
}

#define CP16(dst, src) \
    asm volatile("cp.async.cg.shared.global [%0], [%1], 16;" :: "r"(dst), "l"(src))
#define CP_COMMIT() asm volatile("cp.async.commit_group;" ::: "memory")
#define CP_WAIT(n)  asm volatile("cp.async.wait_group %0;" :: "n"(n) : "memory")

__device__ __forceinline__ void ldsm4(uint32_t r[4], uint32_t addr) {
    asm volatile("ldmatrix.sync.aligned.m8n8.x4.shared.b16 {%0,%1,%2,%3}, [%4];"
                 : "=r"(r[0]), "=r"(r[1]), "=r"(r[2]), "=r"(r[3]) : "r"(addr));
}

__device__ __forceinline__ void mma_bf16(float c[4], const uint32_t a[4],
                                         const uint32_t b[2]) {
    asm volatile(
        "mma.sync.aligned.m16n8k16.row.col.f32.bf16.bf16.f32 "
        "{%0,%1,%2,%3}, {%4,%5,%6,%7}, {%8,%9}, {%0,%1,%2,%3};"
        : "+f"(c[0]), "+f"(c[1]), "+f"(c[2]), "+f"(c[3])
        : "r"(a[0]), "r"(a[1]), "r"(a[2]), "r"(a[3]), "r"(b[0]), "r"(b[1]));
}

__device__ __forceinline__ unsigned ld_acq(unsigned* p) {
    unsigned v;
    asm volatile("ld.acquire.gpu.global.u32 %0, [%1];" : "=r"(v) : "l"(p) : "memory");
    return v;
}
__device__ __forceinline__ void st_rel(unsigned* p, unsigned v) {
    asm volatile("st.release.gpu.global.u32 [%0], %1;" :: "l"(p), "r"(v) : "memory");
}

#define PK_CTAS  128
#define PK_GROUP 32   // CTAs per m-group barrier

// Called by thread 0 of every CTA; group g has PK_GROUP co-resident CTAs.
__device__ __forceinline__ void grid_bar(int g) {
    unsigned ph = ld_acq(&g_bar_phase[g]);
    __threadfence();
    unsigned old = atomicAdd(&g_bar_count[g], 1);
    if (old == PK_GROUP - 1) {
        g_bar_count[g] = 0;
        st_rel(&g_bar_phase[g], ph + 1);
    } else {
        while (ld_acq(&g_bar_phase[g]) == ph) { }
    }
}

// ============================================================================
// Prep: split + transpose a weight [K][N] fp32 -> [N][K] bf16 hi/lo
// ============================================================================
__global__ __launch_bounds__(256) void split_w_kernel(const float* __restrict__ W,
                                                      int which)
{
    __shared__ float tile[32][33];
    __nv_bfloat16* hiOut = which ? g_Whh_hi : g_Wxh_hi;
    __nv_bfloat16* loOut = which ? g_Whh_lo : g_Wxh_lo;
    const int bx = blockIdx.x * 32;   // n block
    const int by = blockIdx.y * 32;   // k block
    const int tx = threadIdx.x & 31;
    const int ty = threadIdx.x >> 5;
    for (int i = ty; i < 32; i += 8)
        tile[i][tx] = W[(size_t)(by + i) * NH + bx + tx];
    __syncthreads();
    for (int i = ty; i < 32; i += 8) {
        float x = tile[tx][i];                 // W[by+tx][bx+i]
        __nv_bfloat16 h = __float2bfloat16(x);
        __nv_bfloat16 l = __float2bfloat16(x - __bfloat162float(h));
        size_t o = (size_t)(bx + i) * NIN + by + tx;
        hiOut[o] = h;
        loOut[o] = l;
    }
}

// ============================================================================
// Prep: split inputs fp32 [M][K] -> g_Ahi/g_Alo bf16 (same layout)
// ============================================================================
__global__ __launch_bounds__(256) void split_a_kernel(const float* __restrict__ A)
{
    const size_t n4 = (size_t)M_TOTAL * NIN / 4;
    size_t i = (size_t)blockIdx.x * blockDim.x + threadIdx.x;
    const size_t stride = (size_t)gridDim.x * blockDim.x;
    for (; i < n4; i += stride) {
        float4 v = ((const float4*)A)[i];
        __nv_bfloat16 h0 = __float2bfloat16(v.x);
        __nv_bfloat16 h1 = __float2bfloat16(v.y);
        __nv_bfloat16 h2 = __float2bfloat16(v.z);
        __nv_bfloat16 h3 = __float2bfloat16(v.w);
        __nv_bfloat162 hp0(h0, h1), hp1(h2, h3);
        __nv_bfloat162 lp0(__float2bfloat16(v.x - __bfloat162float(h0)),
                           __float2bfloat16(v.y - __bfloat162float(h1)));
        __nv_bfloat162 lp1(__float2bfloat16(v.z - __bfloat162float(h2)),
                           __float2bfloat16(v.w - __bfloat162float(h3)));
        ((__nv_bfloat162*)g_Ahi)[i * 2 + 0] = hp0;
        ((__nv_bfloat162*)g_Ahi)[i * 2 + 1] = hp1;
        ((__nv_bfloat162*)g_Alo)[i * 2 + 0] = lp0;
        ((__nv_bfloat162*)g_Alo)[i * 2 + 1] = lp1;
    }
}

// ============================================================================
// Phase 1 GEMM: C[M,N] = Ahi/lo @ Whi/lo^T + bias  (split bf16, HMMA)
// CTA 128x128, 256 thr (8 warps 2x4, warp tile 64x32), K-chunk 32, 3 stages.
// ============================================================================
#define G1_PITCH   40
#define G1_ARR_B   (128 * G1_PITCH * 2)      // 10240 B per array
#define G1_STAGE_B (4 * G1_ARR_B)            // 40960 B per stage
#define G1_SMEM    (3 * G1_STAGE_B)          // 122880 B

__global__ __launch_bounds__(256, 1) void gemm1_kernel(
    const float* __restrict__ bias, float* __restrict__ C)
{
    extern __shared__ char smem[];
    const uint32_t sb0 = smem_u32(smem);
    const int tid  = threadIdx.x;
    const int wid  = tid >> 5;
    const int lane = tid & 31;
    const int m0 = blockIdx.y * 128;
    const int n0 = blockIdx.x * 128;
    const int warp_m = (wid >> 2) * 64;
    const int warp_n = (wid & 3) * 32;

    float acc[4][4][4];
#pragma unroll
    for (int i = 0; i < 4; i++)
#pragma unroll
        for (int j = 0; j < 4; j++)
#pragma unroll
            for (int k = 0; k < 4; k++) acc[i][j][k] = 0.f;

    const int crow = tid >> 2;       // 0..63
    const int cseg = tid & 3;        // 0..3 (16B units)

    auto issue = [&](int c, int s) {
        const uint32_t st = sb0 + s * G1_STAGE_B;
        const int kb = c * 32 + cseg * 8;
#pragma unroll
        for (int h = 0; h < 2; h++) {
            const int r = crow + h * 64;
            const size_t ga = (size_t)(m0 + r) * NIN + kb;
            const size_t gb = (size_t)(n0 + r) * NIN + kb;
            const uint32_t so = r * 80 + cseg * 16;
            CP16(st + so,                  g_Ahi + ga);
            CP16(st + G1_ARR_B + so,       g_Alo + ga);
            CP16(st + 2 * G1_ARR_B + so,   g_Wxh_hi + gb);
            CP16(st + 3 * G1_ARR_B + so,   g_Wxh_lo + gb);
        }
    };

    issue(0, 0); CP_COMMIT();
    issue(1, 1); CP_COMMIT();

    for (int it = 0; it < 32; it++) {
        CP_WAIT(1);
        __syncthreads();
        if (it + 2 < 32) issue(it + 2, (it + 2) % 3);
        CP_COMMIT();

        const uint32_t st = sb0 + (it % 3) * G1_STAGE_B;
#pragma unroll
        for (int ks = 0; ks < 2; ks++) {
            const uint32_t kb = ks * 32;
            uint32_t ah[4][4], al[4][4];
#pragma unroll
            for (int mt = 0; mt < 4; mt++) {
                const int mr = warp_m + mt * 16 + (lane & 15);
                const uint32_t ad = st + mr * 80 + ((lane >> 4) * 16) + kb;
                ldsm4(ah[mt], ad);
                ldsm4(al[mt], ad + G1_ARR_B);
            }
            uint32_t bh[4][2], bl[4][2];
#pragma unroll
            for (int g = 0; g < 2; g++) {
                const int nr = warp_n + g * 16 + (lane & 7) + ((lane >> 4) << 3);
                const uint32_t bd = st + 2 * G1_ARR_B + nr * 80 +
                                    (((lane >> 3) & 1) * 16) + kb;
                uint32_t t[4];
                ldsm4(t, bd);
                bh[g * 2][0] = t[0]; bh[g * 2][1] = t[1];
                bh[g * 2 + 1][0] = t[2]; bh[g * 2 + 1][1] = t[3];
                ldsm4(t, bd + G1_ARR_B);
                bl[g * 2][0] = t[0]; bl[g * 2][1] = t[1];
                bl[g * 2 + 1][0] = t[2]; bl[g * 2 + 1][1] = t[3];
            }
#pragma unroll
            for (int mt = 0; mt < 4; mt++)
#pragma unroll
                for (int nt = 0; nt < 4; nt++) {
                    mma_bf16(acc[mt][nt], ah[mt], bh[nt]);
                    mma_bf16(acc[mt][nt], ah[mt], bl[nt]);
                    mma_bf16(acc[mt][nt], al[mt], bh[nt]);
                }
        }
    }

#pragma unroll
    for (int mt = 0; mt < 4; mt++) {
        const int m = m0 + warp_m + mt * 16 + (lane >> 2);
#pragma unroll
        for (int nt = 0; nt < 4; nt++) {
            const int n = n0 + warp_n + nt * 8 + (lane & 3) * 2;
            const float b0 = bias[n], b1 = bias[n + 1];
            float2 v0 = make_float2(acc[mt][nt][0] + b0, acc[mt][nt][1] + b1);
            float2 v1 = make_float2(acc[mt][nt][2] + b0, acc[mt][nt][3] + b1);
            *(float2*)(C + (size_t)m * NH + n)       = v0;
            *(float2*)(C + (size_t)(m + 8) * NH + n) = v1;
        }
    }
}

// ============================================================================
// t = 0: h0 = tanh(xw[0]); write fp32 out[0] and bf16 hi/lo state buf 0
// ============================================================================
__global__ __launch_bounds__(256) void tanh0_kernel(float* __restrict__ x)
{
    const size_t i = (size_t)blockIdx.x * blockDim.x + threadIdx.x;  // float4 idx
    float4 v = ((const float4*)x)[i];
    v.x = tanhf(v.x); v.y = tanhf(v.y); v.z = tanhf(v.z); v.w = tanhf(v.w);
    ((float4*)x)[i] = v;
    __nv_bfloat16 h0 = __float2bfloat16(v.x);
    __nv_bfloat16 h1 = __float2bfloat16(v.y);
    __nv_bfloat16 h2 = __float2bfloat16(v.z);
    __nv_bfloat16 h3 = __float2bfloat16(v.w);
    ((__nv_bfloat162*)g_Hhi[0])[i * 2 + 0] = __nv_bfloat162(h0, h1);
    ((__nv_bfloat162*)g_Hhi[0])[i * 2 + 1] = __nv_bfloat162(h2, h3);
    ((__nv_bfloat162*)g_Hlo[0])[i * 2 + 0] =
        __nv_bfloat162(__float2bfloat16(v.x - __bfloat162float(h0)),
                       __float2bfloat16(v.y - __bfloat162float(h1)));
    ((__nv_bfloat162*)g_Hlo[0])[i * 2 + 1] =
        __nv_bfloat162(__float2bfloat16(v.z - __bfloat162float(h2)),
                       __float2bfloat16(v.w - __bfloat162float(h3)));
}

// ============================================================================
// Persistent RNN recurrence kernel: t = 1..511, per-m-group barriers.
// 128 CTAs = 4 m-groups (64 rows) x 32 n-blocks (32 cols), 256 threads.
// W_hh hi+lo slice (32 n-rows x 1024 K) RESIDENT in smem (160 KB).
// H streamed per step: K-chunk 64, 3 stages x 20 KB (16 iters/step).
// smem:
//   [0, 81920)         W hi resident: 32 k32-chunks x (32 rows x 80 B)
//   [81920, 163840)    W lo resident
//   [163840, 225280)   H stages: 3 x { sub-chunk j in {0,1}: hi at j*5120,
//                                      lo at j*5120+10240; row pitch 80 B }
// ============================================================================
#define PW_HI    0
#define PW_LO    81920
#define PH_BASE  163840
#define PH_STAGE 20480
#define PH_SUB   5120
#define PH_LO    10240
#define PK_SMEM  225280

__global__ __launch_bounds__(256, 1) void rnn_persist_kernel(float* __restrict__ out)
{
    extern __shared__ char smem[];
    const uint32_t sb = smem_u32(smem);
    const int tid  = threadIdx.x;
    const int wid  = tid >> 5;
    const int lane = tid & 31;
    const int mb = blockIdx.x >> 5;    // 0..3  (barrier group)
    const int nb = blockIdx.x & 31;    // 0..31
    const int m0 = mb * 64;
    const int n0 = nb * 32;
    const int warp_m = (wid >> 1) * 16;   // 0..48
    const int warp_n = (wid & 1) * 16;    // 0 or 16

    // ---- Load resident W_hh slice (hi+lo), chunked K-major, pitch 80B ----
    for (int idx = tid; idx < 4096; idx += 256) {
        const int ch  = idx >> 7;          // 0..31  k32-chunk
        const int r   = (idx >> 2) & 31;   // 0..31  n-row
        const int seg = idx & 3;           // 0..3   16B seg
        const size_t g = (size_t)(n0 + r) * NH + ch * 32 + seg * 8;
        const uint32_t so = sb + ch * 2560 + r * 80 + seg * 16;
        CP16(so + PW_HI, g_Whh_hi + g);
        CP16(so + PW_LO, g_Whh_lo + g);
    }
    CP_COMMIT(); CP_WAIT(0); __syncthreads();

    const int hrow = tid >> 2;   // 0..63
    const int hseg = tid & 3;

    for (int t = 1; t < T_STEPS; t++) {
        const __nv_bfloat16* Hh = g_Hhi[(t - 1) & 1];
        const __nv_bfloat16* Hl = g_Hlo[(t - 1) & 1];
        __nv_bfloat16* HhO = g_Hhi[t & 1];
        __nv_bfloat16* HlO = g_Hlo[t & 1];
        float* X = out + (size_t)t * BATCH * NH;

        // Prefetch this CTA's xw tile into registers
        float2 xwr[2][2];
        {
            const int mrow = m0 + warp_m + (lane >> 2);
#pragma unroll
            for (int half = 0; half < 2; half++)
#pragma unroll
                for (int nt = 0; nt < 2; nt++) {
                    const int m = mrow + half * 8;
                    const int n = n0 + warp_n + nt * 8 + (lane & 3) * 2;
                    xwr[half][nt] = *(const float2*)(X + (size_t)m * NH + n);
                }
        }

        // issue K64 chunk c into stage c%3
        auto issueH = [&](int c) {
            const uint32_t st = sb + PH_BASE + (c % 3) * PH_STAGE +
                                hrow * 80 + hseg * 16;
#pragma unroll
            for (int j = 0; j < 2; j++) {
                const size_t ga = (size_t)(m0 + hrow) * NH + c * 64 + j * 32 + hseg * 8;
                CP16(st + j * PH_SUB,         Hh + ga);
                CP16(st + j * PH_SUB + PH_LO, Hl + ga);
            }
        };
        issueH(0); CP_COMMIT();
        issueH(1); CP_COMMIT();

        float acc[2][4];
#pragma unroll
        for (int i = 0; i < 2; i++)
#pragma unroll
            for (int j = 0; j < 4; j++) acc[i][j] = 0.f;

        for (int it = 0; it < 16; it++) {
            CP_WAIT(1);
            __syncthreads();
            if (it + 2 < 16) issueH(it + 2);   // stage (it+2)%3: not computed, not in flight
            CP_COMMIT();

            const uint32_t hst = sb + PH_BASE + (it % 3) * PH_STAGE;
#pragma unroll
            for (int ks = 0; ks < 4; ks++) {
                const int sub = ks >> 1;
                const uint32_t kb = (ks & 1) * 32;
                uint32_t ah[4], al[4];
                {
                    const uint32_t ad = hst + sub * PH_SUB +
                                        (warp_m + (lane & 15)) * 80 +
                                        ((lane >> 4) * 16) + kb;
                    ldsm4(ah, ad);
                    ldsm4(al, ad + PH_LO);
                }
                uint32_t bh[2][2], bl[2][2];
                {
                    const int nr = warp_n + (lane & 7) + ((lane >> 4) << 3);
                    const uint32_t bd = sb + (it * 2 + sub) * 2560 + nr * 80 +
                                        (((lane >> 3) & 1) * 16) + kb;
                    uint32_t tmp[4];
                    ldsm4(tmp, bd + PW_HI);
                    bh[0][0] = tmp[0]; bh[0][1] = tmp[1];
                    bh[1][0] = tmp[2]; bh[1][1] = tmp[3];
                    ldsm4(tmp, bd + PW_LO);
                    bl[0][0] = tmp[0]; bl[0][1] = tmp[1];
                    bl[1][0] = tmp[2]; bl[1][1] = tmp[3];
                }
#pragma unroll
                for (int nt = 0; nt < 2; nt++) {
                    mma_bf16(acc[nt], ah, bh[nt]);
                    mma_bf16(acc[nt], ah, bl[nt]);
                    mma_bf16(acc[nt], al, bh[nt]);
                }
            }
        }

        // ---- Epilogue: h = tanh(xw + acc); write out + bf16 hi/lo state ----
        {
            const int mrow = m0 + warp_m + (lane >> 2);
#pragma unroll
            for (int half = 0; half < 2; half++) {
                const int m = mrow + half * 8;
#pragma unroll
                for (int nt = 0; nt < 2; nt++) {
                    const int n = n0 + warp_n + nt * 8 + (lane & 3) * 2;
                    const size_t off = (size_t)m * NH + n;
                    const float v0 = tanhf(xwr[half][nt].x + acc[nt][half * 2 + 0]);
                    const float v1 = tanhf(xwr[half][nt].y + acc[nt][half * 2 + 1]);
                    *(float2*)(X + off) = make_float2(v0, v1);
                    const __nv_bfloat16 h0 = __float2bfloat16(v0);
                    const __nv_bfloat16 h1 = __float2bfloat16(v1);
                    *(__nv_bfloat162*)(HhO + off) = __nv_bfloat162(h0, h1);
                    *(__nv_bfloat162*)(HlO + off) = __nv_bfloat162(
                        __float2bfloat16(v0 - __bfloat162float(h0)),
                        __float2bfloat16(v1 - __bfloat162float(h1)));
                    if (t == T_STEPS - 1)
                        *(float2*)(out + (size_t)T_STEPS * BATCH * NH + off) =
                            make_float2(v0, v1);
                }
            }
        }

        // ---- Per-m-group barrier between steps (32 CTAs) ----
        __syncthreads();
        if (tid == 0) grid_bar(mb);
        __syncthreads();
    }
}

// ============================================================================
// Launch
// ============================================================================
extern "C" void kernel_launch(void* const* d_in, const int* in_sizes, int n_in,
                              void* d_out, int out_size)
{
    const float* inputs = (const float*)d_in[0];   // [T, B, NIN]
    const float* W_xh   = (const float*)d_in[1];   // [NIN, NH]
    const float* W_hh   = (const float*)d_in[2];   // [NH, NH]
    const float* b_h    = (const float*)d_in[3];   // [NH]
    float* out = (float*)d_out;                    // [T, B, NH] + [B, NH]

    const size_t step_elems = (size_t)BATCH * NH;  // 262144

    static bool attr_set = false;
    if (!attr_set) {
        cudaFuncSetAttribute(gemm1_kernel,
                             cudaFuncAttributeMaxDynamicSharedMemorySize, G1_SMEM);
        cudaFuncSetAttribute(rnn_persist_kernel,
                             cudaFuncAttributeMaxDynamicSharedMemorySize, PK_SMEM);
        attr_set = true;
    }

    // Prep: split weights (transposed) and inputs into bf16 hi/lo
    {
        dim3 grid(NH / 32, NIN / 32);
        split_w_kernel<<<grid, 256>>>(W_xh, 0);
        split_w_kernel<<<grid, 256>>>(W_hh, 1);
        split_a_kernel<<<8192, 256>>>(inputs);
    }

    // Phase 1: xw = inputs @ W_xh + b_h  -> out[0..T)
    {
        dim3 grid(NH / 128, M_TOTAL / 128);   // (8, 1024)
        gemm1_kernel<<<grid, 256, G1_SMEM>>>(b_h, out);
    }

    // t = 0
    tanh0_kernel<<<(int)(step_elems / 4 / 256), 256>>>(out);

    // t = 1..T-1 in ONE persistent kernel (also writes final_state tail)
    rnn_persist_kernel<<<PK_CTAS, 256, PK_SMEM>>>(out);
}